// round 10
// baseline (speedup 1.0000x reference)
#include <cuda_runtime.h>
#include <cuda_fp16.h>
#include <cstdint>

#define NN 50000
#define D  128
#define BM 128
#define EMAX 640000
#define SCAN_BLOCKS 196   // ceil(50000/256)
#define ASTRIDE 132       // SMEM row stride (words): bank = (4*row + k) % 32

// Scratch: __device__ globals (no allocation allowed).
__device__ __align__(128) __half g_xh [(size_t)NN * D];   // x in fp16
__device__ __align__(128) __half g_h1h[(size_t)NN * D];   // h1 in fp16
__device__ __align__(128) int    g_cnt[NN];
__device__ __align__(128) int    g_rowptr[NN + 1];
__device__ __align__(128) int    g_col[EMAX];
__device__ __align__(128) int    g_bsum[256];
__device__ int g_is64;

// ---------------------------------------------------------------------------
// Fused init: zero g_cnt, convert x -> fp16, block 0 probes edge dtype
// (int64 ids < 2^31 -> all odd 32-bit words zero).
// ---------------------------------------------------------------------------
__global__ void k_init(const float* __restrict__ x,
                       const int* __restrict__ ei32, int n32) {
    long long i = (long long)blockIdx.x * 256 + threadIdx.x;
    if (i < NN) g_cnt[(int)i] = 0;

    long long tot8 = (long long)NN * D / 8;
    if (i < tot8) {
        const float4* p = reinterpret_cast<const float4*>(x) + i * 2;
        float4 a = p[0], b = p[1];
        __half2 h0 = __floats2half2_rn(a.x, a.y);
        __half2 h1 = __floats2half2_rn(a.z, a.w);
        __half2 h2 = __floats2half2_rn(b.x, b.y);
        __half2 h3 = __floats2half2_rn(b.z, b.w);
        uint4 o;
        o.x = *reinterpret_cast<uint32_t*>(&h0);
        o.y = *reinterpret_cast<uint32_t*>(&h1);
        o.z = *reinterpret_cast<uint32_t*>(&h2);
        o.w = *reinterpret_cast<uint32_t*>(&h3);
        reinterpret_cast<uint4*>(g_xh)[i] = o;
    }

    if (blockIdx.x == 0) {
        __shared__ int any_nz;
        if (threadIdx.x == 0) any_nz = 0;
        __syncthreads();
        int limit = n32 < 8192 ? n32 : 8192;
        int found = 0;
        for (int k = threadIdx.x * 2 + 1; k < limit; k += 512)
            if (ei32[k] != 0) { found = 1; break; }
        if (found) atomicOr(&any_nz, 1);
        __syncthreads();
        if (threadIdx.x == 0) g_is64 = any_nz ? 0 : 1;
    }
}

// Low-word-only index read (node ids < 2^31: high word of int64 is zero).
__device__ __forceinline__ int eidx(const void* ei, int i) {
    return g_is64 ? ((const int*)ei)[2 * i] : ((const int*)ei)[i];
}

__global__ void k_hist(const void* __restrict__ ei, int E) {
    int e = blockIdx.x * blockDim.x + threadIdx.x;
    if (e < E) atomicAdd(&g_cnt[eidx(ei, E + e)], 1);
}

__global__ void k_scan1() {
    __shared__ int sh[256];
    int gid = blockIdx.x * 256 + threadIdx.x;
    int v = (gid < NN) ? g_cnt[gid] : 0;
    sh[threadIdx.x] = v;
    __syncthreads();
    for (int off = 1; off < 256; off <<= 1) {
        int t = (threadIdx.x >= off) ? sh[threadIdx.x - off] : 0;
        __syncthreads();
        sh[threadIdx.x] += t;
        __syncthreads();
    }
    if (gid < NN) g_rowptr[gid] = sh[threadIdx.x] - v;
    if (threadIdx.x == 255) g_bsum[blockIdx.x] = sh[255];
}

__global__ void k_scan3(int E) {
    __shared__ int sh[256];
    int t = threadIdx.x;
    sh[t] = (t < blockIdx.x) ? g_bsum[t] : 0;
    __syncthreads();
    for (int off = 128; off > 0; off >>= 1) {
        if (t < off) sh[t] += sh[t + off];
        __syncthreads();
    }
    int base = sh[0];
    int gid = blockIdx.x * 256 + t;
    if (gid < NN) {
        int r = g_rowptr[gid] + base;
        g_rowptr[gid] = r;
        g_cnt[gid] = r;          // cursor for fill
    }
    if (gid == 0) g_rowptr[NN] = E;
}

__global__ void k_fill(const void* __restrict__ ei, int E) {
    int e = blockIdx.x * blockDim.x + threadIdx.x;
    if (e < E) {
        int s = eidx(ei, e);
        int d = eidx(ei, E + e);
        int idx = atomicAdd(&g_cnt[d], 1);
        g_col[idx] = s;
    }
}

// ---------------------------------------------------------------------------
__device__ __forceinline__ uint32_t to_tf32(float f) {
    uint32_t r;
    asm("cvt.rna.tf32.f32 %0, %1;" : "=r"(r) : "f"(f));
    return r;
}

// ---------------------------------------------------------------------------
// FUSED gather + tf32 GEMM:
//   out = relu( mean(feat[neigh]) @ Wl + feat @ Wr + b )
// Phase 1a: per-warp CSR gather of 128 node means -> mean_sm (tf32)
// Phase 1b: stage this block's 128 fp16 feature rows -> xp_sm (tf32)
// Phase 2:  for half in {Wl, Wr}: stage B chunk -> bs_sm; 16 k-steps of
//           m16n8k8 reading A fragments DIRECTLY from mean_sm / xp_sm.
// SMEM: 3 panels of 128 x ASTRIDE(132) uint32 = 198 KB dynamic, 1 block/SM.
// Fragment banks: (4*row + k) % 32 -> conflict-free for A and B loads.
// ---------------------------------------------------------------------------
extern __shared__ uint32_t sm_raw[];

__global__ __launch_bounds__(256) void k_fgemm(
    const float* __restrict__ Wl,
    const float* __restrict__ Wr,
    const float* __restrict__ bias,
    float* __restrict__ outbuf,
    int in_from_h1, int out_to_h1)
{
    uint32_t (*mean_sm)[ASTRIDE] = (uint32_t(*)[ASTRIDE])sm_raw;
    uint32_t (*xp_sm)[ASTRIDE]   = (uint32_t(*)[ASTRIDE])(sm_raw + 128 * ASTRIDE);
    uint32_t (*bs_sm)[ASTRIDE]   = (uint32_t(*)[ASTRIDE])(sm_raw + 2 * 128 * ASTRIDE);

    const int tid  = threadIdx.x;
    const int wid  = tid >> 5;
    const int lane = tid & 31;
    const int half = lane >> 4;    // 0/1: edge parity in gather
    const int li   = lane & 15;    // 16B slice owner within a 256B fp16 row
    const int rowBase = blockIdx.x * BM;
    const __half* feat = in_from_h1 ? g_h1h : g_xh;

    // ---------------- Phase 1a: gather means (warp per node, 16 nodes/warp)
    for (int lr = wid * 16; lr < wid * 16 + 16; lr++) {
        int node = rowBase + lr;
        if (node >= NN) continue;                  // warp-uniform
        int beg = g_rowptr[node], end = g_rowptr[node + 1];

        float acc[8];
#pragma unroll
        for (int q = 0; q < 8; q++) acc[q] = 0.f;

        if (beg < end) {
            for (int j = beg + half; j < end; j += 8) {
                int i1 = j + 2, i2 = j + 4, i3 = j + 6;
                int s0 = g_col[j];
                int s1 = g_col[i1 < end ? i1 : beg];
                int s2 = g_col[i2 < end ? i2 : beg];
                int s3 = g_col[i3 < end ? i3 : beg];
                float m1 = i1 < end ? 1.f : 0.f;
                float m2 = i2 < end ? 1.f : 0.f;
                float m3 = i3 < end ? 1.f : 0.f;
                uint4 u0 = reinterpret_cast<const uint4*>(feat + (size_t)s0 * D)[li];
                uint4 u1 = reinterpret_cast<const uint4*>(feat + (size_t)s1 * D)[li];
                uint4 u2 = reinterpret_cast<const uint4*>(feat + (size_t)s2 * D)[li];
                uint4 u3 = reinterpret_cast<const uint4*>(feat + (size_t)s3 * D)[li];
#pragma unroll
                for (int w = 0; w < 4; w++) {
                    uint32_t c0 = (&u0.x)[w], c1 = (&u1.x)[w];
                    uint32_t c2 = (&u2.x)[w], c3 = (&u3.x)[w];
                    float2 f0 = __half22float2(*reinterpret_cast<__half2*>(&c0));
                    float2 f1 = __half22float2(*reinterpret_cast<__half2*>(&c1));
                    float2 f2 = __half22float2(*reinterpret_cast<__half2*>(&c2));
                    float2 f3 = __half22float2(*reinterpret_cast<__half2*>(&c3));
                    acc[2*w]   += f0.x + m1 * f1.x + m2 * f2.x + m3 * f3.x;
                    acc[2*w+1] += f0.y + m1 * f1.y + m2 * f2.y + m3 * f3.y;
                }
            }
        }
#pragma unroll
        for (int q = 0; q < 8; q++)
            acc[q] += __shfl_xor_sync(0xffffffffu, acc[q], 16);

        if (half == 0) {
            float inv = 1.0f / fmaxf((float)(end - beg), 1.0f);
            uint4 w0 = make_uint4(to_tf32(acc[0]*inv), to_tf32(acc[1]*inv),
                                  to_tf32(acc[2]*inv), to_tf32(acc[3]*inv));
            uint4 w1 = make_uint4(to_tf32(acc[4]*inv), to_tf32(acc[5]*inv),
                                  to_tf32(acc[6]*inv), to_tf32(acc[7]*inv));
            *reinterpret_cast<uint4*>(&mean_sm[lr][li * 8])     = w0;
            *reinterpret_cast<uint4*>(&mean_sm[lr][li * 8 + 4]) = w1;
        }
    }

    // ---------------- Phase 1b: stage own feature rows (fp16 -> tf32)
#pragma unroll
    for (int it = 0; it < 8; it++) {
        int idx = tid + it * 256;          // 0..2047 uint4 slots
        int row = idx >> 4;
        int l2  = idx & 15;
        int node = rowBase + row;
        if (node < NN) {
            uint4 u = reinterpret_cast<const uint4*>(feat + (size_t)node * D)[l2];
            uint4 w0, w1;
            float2 f0 = __half22float2(*reinterpret_cast<__half2*>(&u.x));
            float2 f1 = __half22float2(*reinterpret_cast<__half2*>(&u.y));
            float2 f2 = __half22float2(*reinterpret_cast<__half2*>(&u.z));
            float2 f3 = __half22float2(*reinterpret_cast<__half2*>(&u.w));
            w0 = make_uint4(to_tf32(f0.x), to_tf32(f0.y), to_tf32(f1.x), to_tf32(f1.y));
            w1 = make_uint4(to_tf32(f2.x), to_tf32(f2.y), to_tf32(f3.x), to_tf32(f3.y));
            *reinterpret_cast<uint4*>(&xp_sm[row][l2 * 8])     = w0;
            *reinterpret_cast<uint4*>(&xp_sm[row][l2 * 8 + 4]) = w1;
        }
    }
    __syncthreads();

    // ---------------- Phase 2: two K-halves (Wl then Wr)
    const int grp = lane >> 2;
    const int tig = lane & 3;
    const int warpRow = (wid >> 2) * 64;
    const int warpCol = (wid & 3) * 32;

    float acc[4][4][4];
#pragma unroll
    for (int mt = 0; mt < 4; mt++)
#pragma unroll
        for (int nt = 0; nt < 4; nt++)
#pragma unroll
            for (int q = 0; q < 4; q++) acc[mt][nt][q] = 0.f;

    for (int h = 0; h < 2; h++) {
        const float* W = h ? Wr : Wl;
        // stage B chunk [128 k x 128 cols] -> bs_sm[col][k], k-contiguous
#pragma unroll
        for (int it = 0; it < 16; it++) {
            int lin = tid + it * 256;      // 0..4095: (col, kquad)
            int c  = lin & 127;
            int kq = lin >> 7;             // 0..31
            float f0 = W[(size_t)(kq * 4 + 0) * D + c];
            float f1 = W[(size_t)(kq * 4 + 1) * D + c];
            float f2 = W[(size_t)(kq * 4 + 2) * D + c];
            float f3 = W[(size_t)(kq * 4 + 3) * D + c];
            *reinterpret_cast<uint4*>(&bs_sm[c][kq * 4]) =
                make_uint4(to_tf32(f0), to_tf32(f1), to_tf32(f2), to_tf32(f3));
        }
        __syncthreads();

        const uint32_t (*Asm)[ASTRIDE] = h ? xp_sm : mean_sm;
#pragma unroll
        for (int kk8 = 0; kk8 < 16; kk8++) {
            const int kb8 = kk8 * 8;
            uint32_t a[4][4], b[4][2];
#pragma unroll
            for (int mt = 0; mt < 4; mt++) {
                int r0 = warpRow + mt * 16;
                a[mt][0] = Asm[r0 + grp    ][kb8 + tig];
                a[mt][1] = Asm[r0 + grp + 8][kb8 + tig];
                a[mt][2] = Asm[r0 + grp    ][kb8 + tig + 4];
                a[mt][3] = Asm[r0 + grp + 8][kb8 + tig + 4];
            }
#pragma unroll
            for (int nt = 0; nt < 4; nt++) {
                int cn = warpCol + nt * 8 + grp;
                b[nt][0] = bs_sm[cn][kb8 + tig];
                b[nt][1] = bs_sm[cn][kb8 + tig + 4];
            }
#pragma unroll
            for (int mt = 0; mt < 4; mt++)
#pragma unroll
                for (int nt = 0; nt < 4; nt++) {
                    asm volatile(
                        "mma.sync.aligned.m16n8k8.row.col.f32.tf32.tf32.f32 "
                        "{%0,%1,%2,%3}, {%4,%5,%6,%7}, {%8,%9}, {%0,%1,%2,%3};\n"
                        : "+f"(acc[mt][nt][0]), "+f"(acc[mt][nt][1]),
                          "+f"(acc[mt][nt][2]), "+f"(acc[mt][nt][3])
                        : "r"(a[mt][0]), "r"(a[mt][1]), "r"(a[mt][2]), "r"(a[mt][3]),
                          "r"(b[nt][0]), "r"(b[nt][1]));
                }
        }
        __syncthreads();
    }

    // ---------------- epilogue
#pragma unroll
    for (int nt = 0; nt < 4; nt++) {
        int c = warpCol + nt * 8 + 2 * tig;
        float b0 = bias[c], b1 = bias[c + 1];
#pragma unroll
        for (int mt = 0; mt < 4; mt++) {
            int r = rowBase + warpRow + mt * 16 + grp;
            float v0 = fmaxf(acc[mt][nt][0] + b0, 0.f);
            float v1 = fmaxf(acc[mt][nt][1] + b1, 0.f);
            float v2 = fmaxf(acc[mt][nt][2] + b0, 0.f);
            float v3 = fmaxf(acc[mt][nt][3] + b1, 0.f);
            if (out_to_h1) {
                if (r < NN)
                    *reinterpret_cast<__half2*>(&g_h1h[(size_t)r * D + c]) =
                        __floats2half2_rn(v0, v1);
                if (r + 8 < NN)
                    *reinterpret_cast<__half2*>(&g_h1h[(size_t)(r + 8) * D + c]) =
                        __floats2half2_rn(v2, v3);
            } else {
                if (r < NN)
                    *reinterpret_cast<float2*>(&outbuf[(size_t)r * D + c]) =
                        make_float2(v0, v1);
                if (r + 8 < NN)
                    *reinterpret_cast<float2*>(&outbuf[(size_t)(r + 8) * D + c]) =
                        make_float2(v2, v3);
            }
        }
    }
}

// ---------------------------------------------------------------------------
extern "C" void kernel_launch(void* const* d_in, const int* in_sizes, int n_in,
                              void* d_out, int out_size) {
    const float* x   = (const float*)d_in[0];
    const void*  ei  = d_in[1];
    const float* W1l = (const float*)d_in[2];
    const float* b1  = (const float*)d_in[3];
    const float* W1r = (const float*)d_in[4];
    const float* W2l = (const float*)d_in[5];
    const float* b2  = (const float*)d_in[6];
    const float* W2r = (const float*)d_in[7];
    float*       out = (float*)d_out;

    const int E = in_sizes[1] / 2;
    const int eblocks = (E + 255) / 256;
    const int gemmBlocks = (NN + BM - 1) / BM;
    const int initBlocks = (int)(((long long)NN * D / 8 + 255) / 256);
    const int smemBytes = 3 * 128 * ASTRIDE * 4;   // 202752

    static int attrSet = 0;
    if (!attrSet) {
        cudaFuncSetAttribute(k_fgemm,
            cudaFuncAttributeMaxDynamicSharedMemorySize, smemBytes);
        attrSet = 1;
    }

    k_init<<<initBlocks, 256>>>(x, (const int*)ei, in_sizes[1]);

    // CSR build
    k_hist<<<eblocks, 256>>>(ei, E);
    k_scan1<<<SCAN_BLOCKS, 256>>>();
    k_scan3<<<SCAN_BLOCKS, 256>>>(E);
    k_fill<<<eblocks, 256>>>(ei, E);

    // Layer 1 (fused gather+GEMM) -> g_h1h (fp16)
    k_fgemm<<<gemmBlocks, 256, smemBytes>>>(W1l, W1r, b1, out, 0, 1);
    // Layer 2 -> d_out
    k_fgemm<<<gemmBlocks, 256, smemBytes>>>(W2l, W2r, b2, out, 1, 0);
}